// round 1
// baseline (speedup 1.0000x reference)
#include <cuda_runtime.h>
#include <math.h>

// Problem constants
#define BB   4
#define LL   2048
#define DD   512
#define HH   8
#define HD   64
#define DFF  2048
#define MR   (BB*LL)   // 8192 rows

// ---------------- scratch (device globals: allocation-free) ----------------
__device__ float g_qkv [MR * 3 * DD];   // 50.3 MB
__device__ float g_vals[MR * DD];       // attention output (head-concat)
__device__ float g_tmp [MR * DD];       // proj / ffn2 output
__device__ float g_x1  [MR * DD];       // after first LN (residual for 2nd)
__device__ float g_ff  [MR * DFF];      // ffn hidden

// ---------------------------------------------------------------------------
// Generic SGEMM:  C[M,N] = A[M,K] @ W[N,K]^T + bias[N]   (optional ReLU)
// BM=BN=128, BK=16, 256 threads, 8x8 microtile.
// ---------------------------------------------------------------------------
template<int RELU>
__global__ __launch_bounds__(256)
void sgemm_nt(const float* __restrict__ A, const float* __restrict__ W,
              const float* __restrict__ bias, float* __restrict__ C,
              int M, int N, int K)
{
    __shared__ float As[16][132];
    __shared__ float Bs[16][132];

    const int tid = threadIdx.x;
    const int bm = blockIdx.y * 128;
    const int bn = blockIdx.x * 128;
    const int ty = tid >> 4;        // 0..15
    const int tx = tid & 15;        // 0..15

    const int lr = tid >> 2;        // 0..63
    const int lk = (tid & 3) * 4;   // 0,4,8,12

    const float* Ap = A + (size_t)(bm + lr) * K + lk;
    const float* Wp = W + (size_t)(bn + lr) * K + lk;

    float acc[8][8];
    #pragma unroll
    for (int i = 0; i < 8; i++)
        #pragma unroll
        for (int j = 0; j < 8; j++) acc[i][j] = 0.f;

    for (int k0 = 0; k0 < K; k0 += 16) {
        float4 a0 = *(const float4*)(Ap + k0);
        float4 a1 = *(const float4*)(Ap + (size_t)64 * K + k0);
        float4 b0 = *(const float4*)(Wp + k0);
        float4 b1 = *(const float4*)(Wp + (size_t)64 * K + k0);

        As[lk+0][lr]    = a0.x; As[lk+1][lr]    = a0.y; As[lk+2][lr]    = a0.z; As[lk+3][lr]    = a0.w;
        As[lk+0][lr+64] = a1.x; As[lk+1][lr+64] = a1.y; As[lk+2][lr+64] = a1.z; As[lk+3][lr+64] = a1.w;
        Bs[lk+0][lr]    = b0.x; Bs[lk+1][lr]    = b0.y; Bs[lk+2][lr]    = b0.z; Bs[lk+3][lr]    = b0.w;
        Bs[lk+0][lr+64] = b1.x; Bs[lk+1][lr+64] = b1.y; Bs[lk+2][lr+64] = b1.z; Bs[lk+3][lr+64] = b1.w;
        __syncthreads();

        #pragma unroll
        for (int k = 0; k < 16; k++) {
            float4 av0 = *(float4*)&As[k][ty*8];
            float4 av1 = *(float4*)&As[k][ty*8 + 4];
            float4 bv0 = *(float4*)&Bs[k][tx*8];
            float4 bv1 = *(float4*)&Bs[k][tx*8 + 4];
            float a[8] = {av0.x, av0.y, av0.z, av0.w, av1.x, av1.y, av1.z, av1.w};
            float b[8] = {bv0.x, bv0.y, bv0.z, bv0.w, bv1.x, bv1.y, bv1.z, bv1.w};
            #pragma unroll
            for (int i = 0; i < 8; i++)
                #pragma unroll
                for (int j = 0; j < 8; j++)
                    acc[i][j] += a[i] * b[j];
        }
        __syncthreads();
    }

    float4 bi0 = *(const float4*)&bias[bn + tx*8];
    float4 bi1 = *(const float4*)&bias[bn + tx*8 + 4];
    float bi[8] = {bi0.x, bi0.y, bi0.z, bi0.w, bi1.x, bi1.y, bi1.z, bi1.w};

    #pragma unroll
    for (int i = 0; i < 8; i++) {
        int row = bm + ty*8 + i;
        float v[8];
        #pragma unroll
        for (int j = 0; j < 8; j++) {
            v[j] = acc[i][j] + bi[j];
            if (RELU) v[j] = fmaxf(v[j], 0.f);
        }
        float* cp = C + (size_t)row * N + bn + tx*8;
        *(float4*)(cp)     = make_float4(v[0], v[1], v[2], v[3]);
        *(float4*)(cp + 4) = make_float4(v[4], v[5], v[6], v[7]);
    }
}

// ---------------------------------------------------------------------------
// Flash attention. One block per (q-tile of 64 rows, head, batch).
// Online softmax over 32 s-tiles of 64 columns. fp32 throughout.
// qkv layout: [B, L, 3D] where per-token layout is [head][q(64)|k(64)|v(64)].
// ---------------------------------------------------------------------------
#define QSTR 68   // padded smem row stride (multiple of 4, not of 32)

__global__ __launch_bounds__(256)
void flash_attn(const float* __restrict__ qkv, const int* __restrict__ mask,
                float* __restrict__ vals)
{
    extern __shared__ float sm[];
    float (*Qs)[QSTR]  = (float(*)[QSTR])(sm);
    float (*KVs)[QSTR] = (float(*)[QSTR])(sm + 64*QSTR);
    float (*Ss)[QSTR]  = (float(*)[QSTR])(sm + 2*64*QSTR);
    float* mrow = sm + 3*64*QSTR;
    float* lrow = mrow + 64;
    float* arow = lrow + 64;

    const int tid   = threadIdx.x;
    const int qt    = blockIdx.x;          // 0..31
    const int head  = blockIdx.y;          // 0..7
    const int b     = blockIdx.z;          // 0..3
    const int qbase = qt * 64;
    const int ty = tid >> 4, tx = tid & 15;
    const int row0 = ty * 4, col0 = tx * 4;

    if (tid < 64) { mrow[tid] = -INFINITY; lrow[tid] = 0.f; }

    // load Q tile
    const float* qp = qkv + ((size_t)(b*LL + qbase)) * (3*DD) + head * (3*HD);
    for (int s = tid; s < 64*16; s += 256) {
        int r = s >> 4, c = (s & 15) * 4;
        *(float4*)&Qs[r][c] = *(const float4*)(qp + (size_t)r * (3*DD) + c);
    }

    float acc[4][4];
    #pragma unroll
    for (int i = 0; i < 4; i++)
        #pragma unroll
        for (int j = 0; j < 4; j++) acc[i][j] = 0.f;

    for (int st = 0; st < LL/64; st++) {
        const int sbase = st * 64;
        // load K tile
        const float* kp = qkv + ((size_t)(b*LL + sbase)) * (3*DD) + head * (3*HD) + HD;
        for (int s = tid; s < 64*16; s += 256) {
            int r = s >> 4, c = (s & 15) * 4;
            *(float4*)&KVs[r][c] = *(const float4*)(kp + (size_t)r * (3*DD) + c);
        }
        __syncthreads();

        // S = Q @ K^T (4x4 microtile)
        float sacc[4][4];
        #pragma unroll
        for (int i = 0; i < 4; i++)
            #pragma unroll
            for (int j = 0; j < 4; j++) sacc[i][j] = 0.f;

        #pragma unroll
        for (int d = 0; d < 64; d += 4) {
            float4 qv[4], kv[4];
            #pragma unroll
            for (int i = 0; i < 4; i++) qv[i] = *(float4*)&Qs[row0+i][d];
            #pragma unroll
            for (int j = 0; j < 4; j++) kv[j] = *(float4*)&KVs[col0+j][d];
            #pragma unroll
            for (int i = 0; i < 4; i++)
                #pragma unroll
                for (int j = 0; j < 4; j++)
                    sacc[i][j] += qv[i].x*kv[j].x + qv[i].y*kv[j].y
                                + qv[i].z*kv[j].z + qv[i].w*kv[j].w;
        }
        // scale + mask, write to Ss
        #pragma unroll
        for (int i = 0; i < 4; i++) {
            const int4 mv = *(const int4*)(mask + (size_t)(qbase+row0+i)*LL + sbase + col0);
            Ss[row0+i][col0+0] = (mv.x == 0) ? -INFINITY : sacc[i][0] * 0.125f;
            Ss[row0+i][col0+1] = (mv.y == 0) ? -INFINITY : sacc[i][1] * 0.125f;
            Ss[row0+i][col0+2] = (mv.z == 0) ? -INFINITY : sacc[i][2] * 0.125f;
            Ss[row0+i][col0+3] = (mv.w == 0) ? -INFINITY : sacc[i][3] * 0.125f;
        }
        __syncthreads();

        // online softmax (threads 0..63, one row each)
        if (tid < 64) {
            const int r = tid;
            float mold = mrow[r];
            float rmax = -INFINITY;
            #pragma unroll 8
            for (int c = 0; c < 64; c++) rmax = fmaxf(rmax, Ss[r][c]);
            float mnew = fmaxf(mold, rmax);
            float al = __expf(mold - mnew);
            float s = 0.f;
            #pragma unroll 8
            for (int c = 0; c < 64; c++) {
                float p = __expf(Ss[r][c] - mnew);
                Ss[r][c] = p;
                s += p;
            }
            lrow[r] = lrow[r]*al + s;
            mrow[r] = mnew;
            arow[r] = al;
        }
        // load V tile (overlaps softmax: K no longer needed, Ss reads gated by sync)
        const float* vp = qkv + ((size_t)(b*LL + sbase)) * (3*DD) + head * (3*HD) + 2*HD;
        for (int s = tid; s < 64*16; s += 256) {
            int r = s >> 4, c = (s & 15) * 4;
            *(float4*)&KVs[r][c] = *(const float4*)(vp + (size_t)r * (3*DD) + c);
        }
        __syncthreads();

        // O = O*alpha + P @ V
        float al4[4];
        #pragma unroll
        for (int i = 0; i < 4; i++) al4[i] = arow[row0+i];
        #pragma unroll
        for (int i = 0; i < 4; i++)
            #pragma unroll
            for (int j = 0; j < 4; j++) acc[i][j] *= al4[i];

        #pragma unroll
        for (int k = 0; k < 64; k += 4) {
            float4 pv[4];
            #pragma unroll
            for (int i = 0; i < 4; i++) pv[i] = *(float4*)&Ss[row0+i][k];
            float vv[4][4];
            #pragma unroll
            for (int kk = 0; kk < 4; kk++) {
                float4 t = *(float4*)&KVs[k+kk][col0];
                vv[kk][0]=t.x; vv[kk][1]=t.y; vv[kk][2]=t.z; vv[kk][3]=t.w;
            }
            #pragma unroll
            for (int i = 0; i < 4; i++) {
                float p[4] = {pv[i].x, pv[i].y, pv[i].z, pv[i].w};
                #pragma unroll
                for (int j = 0; j < 4; j++)
                    acc[i][j] += p[0]*vv[0][j] + p[1]*vv[1][j] + p[2]*vv[2][j] + p[3]*vv[3][j];
            }
        }
        __syncthreads();   // protect KVs/Ss before next iteration overwrites
    }

    // normalize + write (head-concat layout [B,L,D])
    #pragma unroll
    for (int i = 0; i < 4; i++) {
        float linv = 1.f / lrow[row0+i];
        float* op = vals + ((size_t)(b*LL + qbase + row0 + i)) * DD + head*HD + col0;
        *(float4*)op = make_float4(acc[i][0]*linv, acc[i][1]*linv,
                                   acc[i][2]*linv, acc[i][3]*linv);
    }
}

// ---------------------------------------------------------------------------
// Fused residual-add + LayerNorm. One block (128 thr) per row of 512.
// ---------------------------------------------------------------------------
__global__ __launch_bounds__(128)
void add_ln(const float* __restrict__ a, const float* __restrict__ bres,
            const float* __restrict__ g, const float* __restrict__ beta,
            float* __restrict__ out)
{
    const int row = blockIdx.x;
    const int tid = threadIdx.x;

    float4 av = ((const float4*)(a    + (size_t)row * DD))[tid];
    float4 bv = ((const float4*)(bres + (size_t)row * DD))[tid];
    float4 x = make_float4(av.x+bv.x, av.y+bv.y, av.z+bv.z, av.w+bv.w);

    float s  = x.x + x.y + x.z + x.w;
    float ss = x.x*x.x + x.y*x.y + x.z*x.z + x.w*x.w;

    #pragma unroll
    for (int o = 16; o > 0; o >>= 1) {
        s  += __shfl_xor_sync(0xffffffffu, s,  o);
        ss += __shfl_xor_sync(0xffffffffu, ss, o);
    }
    __shared__ float red[2][4];
    const int w = tid >> 5, l = tid & 31;
    if (l == 0) { red[0][w] = s; red[1][w] = ss; }
    __syncthreads();
    s  = red[0][0] + red[0][1] + red[0][2] + red[0][3];
    ss = red[1][0] + red[1][1] + red[1][2] + red[1][3];

    const float mean = s * (1.f / DD);
    const float var  = ss * (1.f / DD) - mean * mean;
    const float rstd = rsqrtf(var + 1e-5f);

    float4 gv = ((const float4*)g)[tid];
    float4 ev = ((const float4*)beta)[tid];
    float4 o;
    o.x = (x.x - mean) * rstd * gv.x + ev.x;
    o.y = (x.y - mean) * rstd * gv.y + ev.y;
    o.z = (x.z - mean) * rstd * gv.z + ev.z;
    o.w = (x.w - mean) * rstd * gv.w + ev.w;
    ((float4*)(out + (size_t)row * DD))[tid] = o;
}

// ---------------------------------------------------------------------------
extern "C" void kernel_launch(void* const* d_in, const int* in_sizes, int n_in,
                              void* d_out, int out_size)
{
    const float* src    = (const float*)d_in[0];
    const int*   mask   = (const int*)  d_in[1];
    const float* qkv_w  = (const float*)d_in[2];
    const float* qkv_b  = (const float*)d_in[3];
    const float* out_w  = (const float*)d_in[4];
    const float* out_b  = (const float*)d_in[5];
    const float* w1     = (const float*)d_in[6];
    const float* b1     = (const float*)d_in[7];
    const float* w2     = (const float*)d_in[8];
    const float* b2     = (const float*)d_in[9];
    const float* g1     = (const float*)d_in[10];
    const float* beta1  = (const float*)d_in[11];
    const float* g2     = (const float*)d_in[12];
    const float* beta2  = (const float*)d_in[13];
    float* out = (float*)d_out;

    void* p;
    cudaGetSymbolAddress(&p, g_qkv);  float* qkv  = (float*)p;
    cudaGetSymbolAddress(&p, g_vals); float* vals = (float*)p;
    cudaGetSymbolAddress(&p, g_tmp);  float* tmp  = (float*)p;
    cudaGetSymbolAddress(&p, g_x1);   float* x1   = (float*)p;
    cudaGetSymbolAddress(&p, g_ff);   float* ff   = (float*)p;

    const int smem_attn = (3*64*QSTR + 3*64) * (int)sizeof(float);
    cudaFuncSetAttribute(flash_attn, cudaFuncAttributeMaxDynamicSharedMemorySize, smem_attn);

    // 1) QKV projection: [8192,512] @ [1536,512]^T -> [8192,1536]
    sgemm_nt<0><<<dim3((3*DD)/128, MR/128), 256>>>(src, qkv_w, qkv_b, qkv, MR, 3*DD, DD);

    // 2) flash attention -> g_vals [8192,512]
    flash_attn<<<dim3(LL/64, HH, BB), 256, smem_attn>>>(qkv, mask, vals);

    // 3) output projection
    sgemm_nt<0><<<dim3(DD/128, MR/128), 256>>>(vals, out_w, out_b, tmp, MR, DD, DD);

    // 4) x1 = LN(src + proj)
    add_ln<<<MR, 128>>>(src, tmp, g1, beta1, x1);

    // 5) FFN1 + ReLU: [8192,512] @ [2048,512]^T
    sgemm_nt<1><<<dim3(DFF/128, MR/128), 256>>>(x1, w1, b1, ff, MR, DFF, DD);

    // 6) FFN2: [8192,2048] @ [512,2048]^T
    sgemm_nt<0><<<dim3(DD/128, MR/128), 256>>>(ff, w2, b2, tmp, MR, DD, DFF);

    // 7) out = LN(x1 + ffn2)
    add_ln<<<MR, 128>>>(x1, tmp, g2, beta2, out);
}

// round 4
// speedup vs baseline: 1.2464x; 1.2464x over previous
#include <cuda_runtime.h>
#include <math.h>
#include <stdint.h>

// Problem constants
#define BB   4
#define LL   2048
#define DD   512
#define HH   8
#define HD   64
#define DFF  2048
#define MR   (BB*LL)   // 8192 rows

// ---------------- scratch (device globals: allocation-free) ----------------
__device__ float g_qkv [MR * 3 * DD];
__device__ float g_vals[MR * DD];
__device__ float g_tmp [MR * DD];
__device__ float g_x1  [MR * DD];
__device__ float g_ff  [MR * DFF];

// ---------------------------------------------------------------------------
// tf32 helpers (legacy mma.sync path — supported on base sm_100)
// ---------------------------------------------------------------------------
__device__ __forceinline__ uint32_t f2tf32(float x) {
    uint32_t r;
    asm("cvt.rna.tf32.f32 %0, %1;" : "=r"(r) : "f"(x));
    return r;
}

#define MMA_TF32(d, a, b)                                                      \
    asm volatile("mma.sync.aligned.m16n8k8.row.col.f32.tf32.tf32.f32 "         \
        "{%0,%1,%2,%3}, {%4,%5,%6,%7}, {%8,%9}, {%0,%1,%2,%3};"                \
        : "+f"((d)[0]), "+f"((d)[1]), "+f"((d)[2]), "+f"((d)[3])               \
        : "r"((a)[0]), "r"((a)[1]), "r"((a)[2]), "r"((a)[3]),                  \
          "r"((b)[0]), "r"((b)[1]))

// ---------------------------------------------------------------------------
// mma.sync tf32 GEMM:  C[M,N] = A[M,K] @ W[N,K]^T + bias[N]  (optional ReLU)
// BM=BN=128, BK=16, 256 thr (8 warps, 2m x 4n), warp tile 64x32.
// Operands rounded to tf32 (cvt.rna) at smem-store time -> MMA truncation
// is lossless; fp32 accumulate.
// ---------------------------------------------------------------------------
#define SPAD 20   // smem row stride in floats (16 data + 4 pad)

template<int RELU>
__global__ __launch_bounds__(256, 2)
void mma_gemm(const float* __restrict__ A, const float* __restrict__ W,
              const float* __restrict__ bias, float* __restrict__ C,
              int M, int N, int K)
{
    __shared__ float As[128 * SPAD];
    __shared__ float Bs[128 * SPAD];

    const int tid  = threadIdx.x;
    const int wid  = tid >> 5, lane = tid & 31;
    const int grp  = lane >> 2, qd = lane & 3;
    const int wm   = (wid & 1) * 64;       // warp row offset
    const int wn   = (wid >> 1) * 32;      // warp col offset
    const int bm   = blockIdx.y * 128;
    const int bn   = blockIdx.x * 128;

    const int lrow = tid >> 1;             // 0..127
    const int lk8  = (tid & 1) * 8;        // 0 or 8

    const float* Ap = A + (size_t)(bm + lrow) * K + lk8;
    const float* Wp = W + (size_t)(bn + lrow) * K + lk8;

    float acc[4][4][4];
    #pragma unroll
    for (int i = 0; i < 4; i++)
        #pragma unroll
        for (int j = 0; j < 4; j++)
            #pragma unroll
            for (int r = 0; r < 4; r++) acc[i][j][r] = 0.f;

    float4 ra0 = *(const float4*)(Ap);
    float4 ra1 = *(const float4*)(Ap + 4);
    float4 rb0 = *(const float4*)(Wp);
    float4 rb1 = *(const float4*)(Wp + 4);

    const int NS = K >> 4;
    for (int s = 0; s < NS; ++s) {
        // store current stage (rounded to tf32)
        uint32_t* pa = (uint32_t*)&As[lrow * SPAD + lk8];
        uint32_t* pb = (uint32_t*)&Bs[lrow * SPAD + lk8];
        pa[0] = f2tf32(ra0.x); pa[1] = f2tf32(ra0.y); pa[2] = f2tf32(ra0.z); pa[3] = f2tf32(ra0.w);
        pa[4] = f2tf32(ra1.x); pa[5] = f2tf32(ra1.y); pa[6] = f2tf32(ra1.z); pa[7] = f2tf32(ra1.w);
        pb[0] = f2tf32(rb0.x); pb[1] = f2tf32(rb0.y); pb[2] = f2tf32(rb0.z); pb[3] = f2tf32(rb0.w);
        pb[4] = f2tf32(rb1.x); pb[5] = f2tf32(rb1.y); pb[6] = f2tf32(rb1.z); pb[7] = f2tf32(rb1.w);
        __syncthreads();

        // prefetch next stage into registers (overlaps compute)
        if (s + 1 < NS) {
            const float* An = Ap + (size_t)(s + 1) * 16;
            const float* Wn = Wp + (size_t)(s + 1) * 16;
            ra0 = *(const float4*)(An);
            ra1 = *(const float4*)(An + 4);
            rb0 = *(const float4*)(Wn);
            rb1 = *(const float4*)(Wn + 4);
        }

        // compute: 2 k-steps of 8
        #pragma unroll
        for (int ks = 0; ks < 2; ++ks) {
            const int kb = ks * 8;
            uint32_t af[4][4], bf[4][2];
            #pragma unroll
            for (int mt = 0; mt < 4; ++mt) {
                const int r = wm + mt * 16;
                af[mt][0] = __float_as_uint(As[(r + grp    ) * SPAD + kb + qd]);
                af[mt][1] = __float_as_uint(As[(r + grp + 8) * SPAD + kb + qd]);
                af[mt][2] = __float_as_uint(As[(r + grp    ) * SPAD + kb + qd + 4]);
                af[mt][3] = __float_as_uint(As[(r + grp + 8) * SPAD + kb + qd + 4]);
            }
            #pragma unroll
            for (int nt = 0; nt < 4; ++nt) {
                const int n = wn + nt * 8 + grp;
                bf[nt][0] = __float_as_uint(Bs[n * SPAD + kb + qd]);
                bf[nt][1] = __float_as_uint(Bs[n * SPAD + kb + qd + 4]);
            }
            #pragma unroll
            for (int mt = 0; mt < 4; ++mt)
                #pragma unroll
                for (int nt = 0; nt < 4; ++nt)
                    MMA_TF32(acc[mt][nt], af[mt], bf[nt]);
        }
        __syncthreads();
    }

    // epilogue: bias (+ReLU), float2 stores
    #pragma unroll
    for (int mt = 0; mt < 4; ++mt) {
        const int row = bm + wm + mt * 16 + grp;
        #pragma unroll
        for (int nt = 0; nt < 4; ++nt) {
            const int col = bn + wn + nt * 8 + 2 * qd;
            const float2 bv = *(const float2*)&bias[col];
            float2 o0, o1;
            o0.x = acc[mt][nt][0] + bv.x; o0.y = acc[mt][nt][1] + bv.y;
            o1.x = acc[mt][nt][2] + bv.x; o1.y = acc[mt][nt][3] + bv.y;
            if (RELU) {
                o0.x = fmaxf(o0.x, 0.f); o0.y = fmaxf(o0.y, 0.f);
                o1.x = fmaxf(o1.x, 0.f); o1.y = fmaxf(o1.y, 0.f);
            }
            *(float2*)(C + (size_t)row * N + col)       = o0;
            *(float2*)(C + (size_t)(row + 8) * N + col) = o1;
        }
    }
}

// ---------------------------------------------------------------------------
// Flash attention (unchanged). One block per (64 q-rows, head, batch).
// ---------------------------------------------------------------------------
#define QSTR 68

__global__ __launch_bounds__(256)
void flash_attn(const float* __restrict__ qkv, const int* __restrict__ mask,
                float* __restrict__ vals)
{
    extern __shared__ float sm[];
    float (*Qs)[QSTR]  = (float(*)[QSTR])(sm);
    float (*KVs)[QSTR] = (float(*)[QSTR])(sm + 64*QSTR);
    float (*Ss)[QSTR]  = (float(*)[QSTR])(sm + 2*64*QSTR);
    float* mrow = sm + 3*64*QSTR;
    float* lrow = mrow + 64;
    float* arow = lrow + 64;

    const int tid   = threadIdx.x;
    const int qt    = blockIdx.x;
    const int head  = blockIdx.y;
    const int b     = blockIdx.z;
    const int qbase = qt * 64;
    const int ty = tid >> 4, tx = tid & 15;
    const int row0 = ty * 4, col0 = tx * 4;

    if (tid < 64) { mrow[tid] = -INFINITY; lrow[tid] = 0.f; }

    const float* qp = qkv + ((size_t)(b*LL + qbase)) * (3*DD) + head * (3*HD);
    for (int s = tid; s < 64*16; s += 256) {
        int r = s >> 4, c = (s & 15) * 4;
        *(float4*)&Qs[r][c] = *(const float4*)(qp + (size_t)r * (3*DD) + c);
    }

    float acc[4][4];
    #pragma unroll
    for (int i = 0; i < 4; i++)
        #pragma unroll
        for (int j = 0; j < 4; j++) acc[i][j] = 0.f;

    for (int st = 0; st < LL/64; st++) {
        const int sbase = st * 64;
        const float* kp = qkv + ((size_t)(b*LL + sbase)) * (3*DD) + head * (3*HD) + HD;
        for (int s = tid; s < 64*16; s += 256) {
            int r = s >> 4, c = (s & 15) * 4;
            *(float4*)&KVs[r][c] = *(const float4*)(kp + (size_t)r * (3*DD) + c);
        }
        __syncthreads();

        float sacc[4][4];
        #pragma unroll
        for (int i = 0; i < 4; i++)
            #pragma unroll
            for (int j = 0; j < 4; j++) sacc[i][j] = 0.f;

        #pragma unroll
        for (int d = 0; d < 64; d += 4) {
            float4 qv[4], kv[4];
            #pragma unroll
            for (int i = 0; i < 4; i++) qv[i] = *(float4*)&Qs[row0+i][d];
            #pragma unroll
            for (int j = 0; j < 4; j++) kv[j] = *(float4*)&KVs[col0+j][d];
            #pragma unroll
            for (int i = 0; i < 4; i++)
                #pragma unroll
                for (int j = 0; j < 4; j++)
                    sacc[i][j] += qv[i].x*kv[j].x + qv[i].y*kv[j].y
                                + qv[i].z*kv[j].z + qv[i].w*kv[j].w;
        }
        #pragma unroll
        for (int i = 0; i < 4; i++) {
            const int4 mv = *(const int4*)(mask + (size_t)(qbase+row0+i)*LL + sbase + col0);
            Ss[row0+i][col0+0] = (mv.x == 0) ? -INFINITY : sacc[i][0] * 0.125f;
            Ss[row0+i][col0+1] = (mv.y == 0) ? -INFINITY : sacc[i][1] * 0.125f;
            Ss[row0+i][col0+2] = (mv.z == 0) ? -INFINITY : sacc[i][2] * 0.125f;
            Ss[row0+i][col0+3] = (mv.w == 0) ? -INFINITY : sacc[i][3] * 0.125f;
        }
        __syncthreads();

        if (tid < 64) {
            const int r = tid;
            float mold = mrow[r];
            float rmax = -INFINITY;
            #pragma unroll 8
            for (int c = 0; c < 64; c++) rmax = fmaxf(rmax, Ss[r][c]);
            float mnew = fmaxf(mold, rmax);
            float al = __expf(mold - mnew);
            float s = 0.f;
            #pragma unroll 8
            for (int c = 0; c < 64; c++) {
                float pp = __expf(Ss[r][c] - mnew);
                Ss[r][c] = pp;
                s += pp;
            }
            lrow[r] = lrow[r]*al + s;
            mrow[r] = mnew;
            arow[r] = al;
        }
        const float* vp = qkv + ((size_t)(b*LL + sbase)) * (3*DD) + head * (3*HD) + 2*HD;
        for (int s = tid; s < 64*16; s += 256) {
            int r = s >> 4, c = (s & 15) * 4;
            *(float4*)&KVs[r][c] = *(const float4*)(vp + (size_t)r * (3*DD) + c);
        }
        __syncthreads();

        float al4[4];
        #pragma unroll
        for (int i = 0; i < 4; i++) al4[i] = arow[row0+i];
        #pragma unroll
        for (int i = 0; i < 4; i++)
            #pragma unroll
            for (int j = 0; j < 4; j++) acc[i][j] *= al4[i];

        #pragma unroll
        for (int k = 0; k < 64; k += 4) {
            float4 pv[4];
            #pragma unroll
            for (int i = 0; i < 4; i++) pv[i] = *(float4*)&Ss[row0+i][k];
            float vv[4][4];
            #pragma unroll
            for (int kk = 0; kk < 4; kk++) {
                float4 t = *(float4*)&KVs[k+kk][col0];
                vv[kk][0]=t.x; vv[kk][1]=t.y; vv[kk][2]=t.z; vv[kk][3]=t.w;
            }
            #pragma unroll
            for (int i = 0; i < 4; i++) {
                float p[4] = {pv[i].x, pv[i].y, pv[i].z, pv[i].w};
                #pragma unroll
                for (int j = 0; j < 4; j++)
                    acc[i][j] += p[0]*vv[0][j] + p[1]*vv[1][j] + p[2]*vv[2][j] + p[3]*vv[3][j];
            }
        }
        __syncthreads();
    }

    #pragma unroll
    for (int i = 0; i < 4; i++) {
        float linv = 1.f / lrow[row0+i];
        float* op = vals + ((size_t)(b*LL + qbase + row0 + i)) * DD + head*HD + col0;
        *(float4*)op = make_float4(acc[i][0]*linv, acc[i][1]*linv,
                                   acc[i][2]*linv, acc[i][3]*linv);
    }
}

// ---------------------------------------------------------------------------
// Fused residual-add + LayerNorm (unchanged).
// ---------------------------------------------------------------------------
__global__ __launch_bounds__(128)
void add_ln(const float* __restrict__ a, const float* __restrict__ bres,
            const float* __restrict__ g, const float* __restrict__ beta,
            float* __restrict__ out)
{
    const int row = blockIdx.x;
    const int tid = threadIdx.x;

    float4 av = ((const float4*)(a    + (size_t)row * DD))[tid];
    float4 bv = ((const float4*)(bres + (size_t)row * DD))[tid];
    float4 x = make_float4(av.x+bv.x, av.y+bv.y, av.z+bv.z, av.w+bv.w);

    float s  = x.x + x.y + x.z + x.w;
    float ss = x.x*x.x + x.y*x.y + x.z*x.z + x.w*x.w;

    #pragma unroll
    for (int o = 16; o > 0; o >>= 1) {
        s  += __shfl_xor_sync(0xffffffffu, s,  o);
        ss += __shfl_xor_sync(0xffffffffu, ss, o);
    }
    __shared__ float red[2][4];
    const int w = tid >> 5, l = tid & 31;
    if (l == 0) { red[0][w] = s; red[1][w] = ss; }
    __syncthreads();
    s  = red[0][0] + red[0][1] + red[0][2] + red[0][3];
    ss = red[1][0] + red[1][1] + red[1][2] + red[1][3];

    const float mean = s * (1.f / DD);
    const float var  = ss * (1.f / DD) - mean * mean;
    const float rstd = rsqrtf(var + 1e-5f);

    float4 gv = ((const float4*)g)[tid];
    float4 ev = ((const float4*)beta)[tid];
    float4 o;
    o.x = (x.x - mean) * rstd * gv.x + ev.x;
    o.y = (x.y - mean) * rstd * gv.y + ev.y;
    o.z = (x.z - mean) * rstd * gv.z + ev.z;
    o.w = (x.w - mean) * rstd * gv.w + ev.w;
    ((float4*)(out + (size_t)row * DD))[tid] = o;
}

// ---------------------------------------------------------------------------
extern "C" void kernel_launch(void* const* d_in, const int* in_sizes, int n_in,
                              void* d_out, int out_size)
{
    const float* src    = (const float*)d_in[0];
    const int*   mask   = (const int*)  d_in[1];
    const float* qkv_w  = (const float*)d_in[2];
    const float* qkv_b  = (const float*)d_in[3];
    const float* out_w  = (const float*)d_in[4];
    const float* out_b  = (const float*)d_in[5];
    const float* w1     = (const float*)d_in[6];
    const float* b1     = (const float*)d_in[7];
    const float* w2     = (const float*)d_in[8];
    const float* b2     = (const float*)d_in[9];
    const float* g1     = (const float*)d_in[10];
    const float* beta1  = (const float*)d_in[11];
    const float* g2     = (const float*)d_in[12];
    const float* beta2  = (const float*)d_in[13];
    float* out = (float*)d_out;

    void* p;
    cudaGetSymbolAddress(&p, g_qkv);  float* qkv  = (float*)p;
    cudaGetSymbolAddress(&p, g_vals); float* vals = (float*)p;
    cudaGetSymbolAddress(&p, g_tmp);  float* tmp  = (float*)p;
    cudaGetSymbolAddress(&p, g_x1);   float* x1   = (float*)p;
    cudaGetSymbolAddress(&p, g_ff);   float* ff   = (float*)p;

    const int smem_attn = (3*64*QSTR + 3*64) * (int)sizeof(float);
    cudaFuncSetAttribute(flash_attn, cudaFuncAttributeMaxDynamicSharedMemorySize, smem_attn);

    // 1) QKV projection: [8192,512] @ [1536,512]^T -> [8192,1536]
    mma_gemm<0><<<dim3((3*DD)/128, MR/128), 256>>>(src, qkv_w, qkv_b, qkv, MR, 3*DD, DD);

    // 2) flash attention -> g_vals [8192,512]
    flash_attn<<<dim3(LL/64, HH, BB), 256, smem_attn>>>(qkv, mask, vals);

    // 3) output projection
    mma_gemm<0><<<dim3(DD/128, MR/128), 256>>>(vals, out_w, out_b, tmp, MR, DD, DD);

    // 4) x1 = LN(src + proj)
    add_ln<<<MR, 128>>>(src, tmp, g1, beta1, x1);

    // 5) FFN1 + ReLU: [8192,512] @ [2048,512]^T
    mma_gemm<1><<<dim3(DFF/128, MR/128), 256>>>(x1, w1, b1, ff, MR, DFF, DD);

    // 6) FFN2: [8192,2048] @ [512,2048]^T
    mma_gemm<0><<<dim3(DD/128, MR/128), 256>>>(ff, w2, b2, tmp, MR, DD, DFF);

    // 7) out = LN(x1 + ffn2)
    add_ln<<<MR, 128>>>(x1, tmp, g2, beta2, out);
}

// round 5
// speedup vs baseline: 3.7950x; 3.0448x over previous
#include <cuda_runtime.h>
#include <math.h>
#include <stdint.h>

// Problem constants
#define BB   4
#define LL   2048
#define DD   512
#define HH   8
#define HD   64
#define DFF  2048
#define MR   (BB*LL)   // 8192 rows

// ---------------- scratch (device globals: allocation-free) ----------------
__device__ float g_qkv [MR * 3 * DD];
__device__ float g_vals[MR * DD];
__device__ float g_tmp [MR * DD];
__device__ float g_x1  [MR * DD];
__device__ float g_ff  [MR * DFF];
__device__ int   g_mflag[16 * 32];   // per (128-row qtile, 64-col stile) all-ones flag

// ---------------------------------------------------------------------------
// tf32 helpers (legacy mma.sync path — supported on base sm_100)
// ---------------------------------------------------------------------------
__device__ __forceinline__ uint32_t f2tf32(float x) {
    uint32_t r;
    asm("cvt.rna.tf32.f32 %0, %1;" : "=r"(r) : "f"(x));
    return r;
}

#define MMA_TF32(d, a, b)                                                      \
    asm volatile("mma.sync.aligned.m16n8k8.row.col.f32.tf32.tf32.f32 "         \
        "{%0,%1,%2,%3}, {%4,%5,%6,%7}, {%8,%9}, {%0,%1,%2,%3};"                \
        : "+f"((d)[0]), "+f"((d)[1]), "+f"((d)[2]), "+f"((d)[3])               \
        : "r"((a)[0]), "r"((a)[1]), "r"((a)[2]), "r"((a)[3]),                  \
          "r"((b)[0]), "r"((b)[1]))

// ---------------------------------------------------------------------------
// mma.sync tf32 GEMM:  C[M,N] = A[M,K] @ W[N,K]^T + bias[N]  (optional ReLU)
// BM=BN=128, BK=16, 256 thr (8 warps, 2m x 4n), warp tile 64x32.
// Double-buffered smem (1 sync/stage). K-interleaved layout: within each
// 8-k group, slot(k) = (k&3)*2 + (k>>2), so fragment pairs (qd, qd+4) are
// adjacent -> LDS.64 fragment loads. SPAD=24 is conflict-free for the v2
// loads in both 16-lane phases.
// ---------------------------------------------------------------------------
#define SPAD 24
#define GEMM_SMEM (2 * 2 * 128 * SPAD * 4)   // 49152 bytes

template<int RELU>
__global__ __launch_bounds__(256, 2)
void mma_gemm(const float* __restrict__ A, const float* __restrict__ W,
              const float* __restrict__ bias, float* __restrict__ C,
              int M, int N, int K)
{
    extern __shared__ float gsm[];
    float* As = gsm;                       // [2][128*SPAD]
    float* Bs = gsm + 2 * 128 * SPAD;      // [2][128*SPAD]

    const int tid  = threadIdx.x;
    const int wid  = tid >> 5, lane = tid & 31;
    const int grp  = lane >> 2, qd = lane & 3;
    const int wm   = (wid & 1) * 64;
    const int wn   = (wid >> 1) * 32;
    const int bm   = blockIdx.y * 128;
    const int bn   = blockIdx.x * 128;

    const int lrow = tid >> 1;             // 0..127
    const int lk8  = (tid & 1) * 8;        // 0 or 8

    const float* Ap = A + (size_t)(bm + lrow) * K + lk8;
    const float* Wp = W + (size_t)(bn + lrow) * K + lk8;

    float acc[4][4][4];
    #pragma unroll
    for (int i = 0; i < 4; i++)
        #pragma unroll
        for (int j = 0; j < 4; j++)
            #pragma unroll
            for (int r = 0; r < 4; r++) acc[i][j][r] = 0.f;

    float4 ra0 = *(const float4*)(Ap);
    float4 ra1 = *(const float4*)(Ap + 4);
    float4 rb0 = *(const float4*)(Wp);
    float4 rb1 = *(const float4*)(Wp + 4);

    // store one stage (tf32-rounded, k-interleaved) into buffer bf
    auto store_stage = [&](int bf) {
        uint32_t* pa = (uint32_t*)&As[bf * 128 * SPAD + lrow * SPAD + lk8];
        uint32_t* pb = (uint32_t*)&Bs[bf * 128 * SPAD + lrow * SPAD + lk8];
        // slots [0..3] = k {0,4,1,5}; slots [4..7] = k {2,6,3,7} (within lk8 group)
        pa[0] = f2tf32(ra0.x); pa[1] = f2tf32(ra1.x); pa[2] = f2tf32(ra0.y); pa[3] = f2tf32(ra1.y);
        pa[4] = f2tf32(ra0.z); pa[5] = f2tf32(ra1.z); pa[6] = f2tf32(ra0.w); pa[7] = f2tf32(ra1.w);
        pb[0] = f2tf32(rb0.x); pb[1] = f2tf32(rb1.x); pb[2] = f2tf32(rb0.y); pb[3] = f2tf32(rb1.y);
        pb[4] = f2tf32(rb0.z); pb[5] = f2tf32(rb1.z); pb[6] = f2tf32(rb0.w); pb[7] = f2tf32(rb1.w);
    };

    store_stage(0);
    __syncthreads();

    const int NS = K >> 4;
    for (int s = 0; s < NS; ++s) {
        const int p = s & 1;
        if (s + 1 < NS) {                  // prefetch next stage into registers
            const float* An = Ap + (size_t)(s + 1) * 16;
            const float* Wn = Wp + (size_t)(s + 1) * 16;
            ra0 = *(const float4*)(An);
            ra1 = *(const float4*)(An + 4);
            rb0 = *(const float4*)(Wn);
            rb1 = *(const float4*)(Wn + 4);
        }
        const float* Ab = &As[p * 128 * SPAD];
        const float* Bb = &Bs[p * 128 * SPAD];
        #pragma unroll
        for (int ks = 0; ks < 2; ++ks) {
            const int kb = ks * 8;
            uint32_t af[4][4], bf[4][2];
            #pragma unroll
            for (int mt = 0; mt < 4; ++mt) {
                const int r = wm + mt * 16 + grp;
                uint2 a02 = *(const uint2*)&Ab[r * SPAD + kb + 2 * qd];
                uint2 a13 = *(const uint2*)&Ab[(r + 8) * SPAD + kb + 2 * qd];
                af[mt][0] = a02.x; af[mt][1] = a13.x;
                af[mt][2] = a02.y; af[mt][3] = a13.y;
            }
            #pragma unroll
            for (int nt = 0; nt < 4; ++nt) {
                const int n = wn + nt * 8 + grp;
                uint2 b01 = *(const uint2*)&Bb[n * SPAD + kb + 2 * qd];
                bf[nt][0] = b01.x; bf[nt][1] = b01.y;
            }
            #pragma unroll
            for (int mt = 0; mt < 4; ++mt)
                #pragma unroll
                for (int nt = 0; nt < 4; ++nt)
                    MMA_TF32(acc[mt][nt], af[mt], bf[nt]);
        }
        if (s + 1 < NS) store_stage(p ^ 1);
        __syncthreads();
    }

    // epilogue: bias (+ReLU), float2 stores
    #pragma unroll
    for (int mt = 0; mt < 4; ++mt) {
        const int row = bm + wm + mt * 16 + grp;
        #pragma unroll
        for (int nt = 0; nt < 4; ++nt) {
            const int col = bn + wn + nt * 8 + 2 * qd;
            const float2 bv = *(const float2*)&bias[col];
            float2 o0, o1;
            o0.x = acc[mt][nt][0] + bv.x; o0.y = acc[mt][nt][1] + bv.y;
            o1.x = acc[mt][nt][2] + bv.x; o1.y = acc[mt][nt][3] + bv.y;
            if (RELU) {
                o0.x = fmaxf(o0.x, 0.f); o0.y = fmaxf(o0.y, 0.f);
                o1.x = fmaxf(o1.x, 0.f); o1.y = fmaxf(o1.y, 0.f);
            }
            *(float2*)(C + (size_t)row * N + col)       = o0;
            *(float2*)(C + (size_t)(row + 8) * N + col) = o1;
        }
    }
}

// ---------------------------------------------------------------------------
// mask tile flags: flags[qt*32+st] = 1 iff mask[qt*128..+128)[st*64..+64) all !=0
// ---------------------------------------------------------------------------
__global__ __launch_bounds__(256)
void mask_flags(const int* __restrict__ mask, int* __restrict__ flags)
{
    const int idx = blockIdx.x;            // 0..511
    const int qt = idx >> 5, st = idx & 31;
    const int tid = threadIdx.x;
    int ok = 1;
    for (int i = tid; i < 128 * 64; i += 256) {
        int r = qt * 128 + (i >> 6);
        int c = st * 64 + (i & 63);
        ok &= (mask[(size_t)r * LL + c] != 0);
    }
    int all = __syncthreads_and(ok);
    if (tid == 0) flags[idx] = all;
}

// ---------------------------------------------------------------------------
// Flash attention via mma.sync tf32.
// CTA: 128 q-rows, 8 warps (each m16). S-tile = 64 keys. P kept in registers;
// S C-frag -> PV A-frag via intra-quad shfl (no smem round-trip, no syncs
// between softmax and PV). Q/K smem stride 68, V stride 72 (conflict-free).
// ---------------------------------------------------------------------------
#define ASTR 68
#define VSTR 72
#define ATT_SMEM ((128 * ASTR + 64 * ASTR + 64 * VSTR) * 4)   // 70656 bytes

__global__ __launch_bounds__(256)
void flash_attn_mma(const float* __restrict__ qkv, const int* __restrict__ mask,
                    const int* __restrict__ flags, float* __restrict__ vals)
{
    extern __shared__ float sm[];
    float* Qs = sm;                        // [128][ASTR]
    float* Ks = sm + 128 * ASTR;           // [64][ASTR]
    float* Vs = Ks + 64 * ASTR;            // [64][VSTR]

    const int tid  = threadIdx.x;
    const int wid  = tid >> 5, lane = tid & 31;
    const int grp  = lane >> 2, qd = lane & 3;
    const int qt   = blockIdx.x;           // 0..15
    const int head = blockIdx.y;           // 0..7
    const int b    = blockIdx.z;           // 0..3
    const int qbase = qt * 128;
    const int m0   = wid * 16;

    // load Q tile (tf32-rounded)
    const float* qp = qkv + ((size_t)(b * LL + qbase)) * (3 * DD) + head * (3 * HD);
    for (int s = tid; s < 128 * 16; s += 256) {
        int r = s >> 4, c = (s & 15) * 4;
        float4 v = *(const float4*)(qp + (size_t)r * (3 * DD) + c);
        uint32_t* dst = (uint32_t*)&Qs[r * ASTR + c];
        dst[0] = f2tf32(v.x); dst[1] = f2tf32(v.y);
        dst[2] = f2tf32(v.z); dst[3] = f2tf32(v.w);
    }

    float o[8][4];
    #pragma unroll
    for (int nt = 0; nt < 8; ++nt)
        #pragma unroll
        for (int r = 0; r < 4; ++r) o[nt][r] = 0.f;
    float m_0 = -INFINITY, m_1 = -INFINITY, l_0 = 0.f, l_1 = 0.f;

    for (int st = 0; st < LL / 64; ++st) {
        __syncthreads();                   // previous-tile smem reads done
        const int sbase = st * 64;
        const float* kp = qkv + ((size_t)(b * LL + sbase)) * (3 * DD) + head * (3 * HD) + HD;
        const float* vp = kp + HD;
        for (int s = tid; s < 64 * 16; s += 256) {
            int r = s >> 4, c = (s & 15) * 4;
            float4 kv = *(const float4*)(kp + (size_t)r * (3 * DD) + c);
            float4 vv = *(const float4*)(vp + (size_t)r * (3 * DD) + c);
            uint32_t* dk = (uint32_t*)&Ks[r * ASTR + c];
            uint32_t* dv = (uint32_t*)&Vs[r * VSTR + c];
            dk[0] = f2tf32(kv.x); dk[1] = f2tf32(kv.y);
            dk[2] = f2tf32(kv.z); dk[3] = f2tf32(kv.w);
            dv[0] = f2tf32(vv.x); dv[1] = f2tf32(vv.y);
            dv[2] = f2tf32(vv.z); dv[3] = f2tf32(vv.w);
        }
        __syncthreads();

        // ---- S = (Q @ K^T) * 0.125 ----
        float sacc[8][4];
        #pragma unroll
        for (int nt = 0; nt < 8; ++nt)
            #pragma unroll
            for (int r = 0; r < 4; ++r) sacc[nt][r] = 0.f;

        #pragma unroll
        for (int ks = 0; ks < 8; ++ks) {
            const int k0 = ks * 8;
            uint32_t a[4];
            a[0] = __float_as_uint(Qs[(m0 + grp    ) * ASTR + k0 + qd]);
            a[1] = __float_as_uint(Qs[(m0 + grp + 8) * ASTR + k0 + qd]);
            a[2] = __float_as_uint(Qs[(m0 + grp    ) * ASTR + k0 + qd + 4]);
            a[3] = __float_as_uint(Qs[(m0 + grp + 8) * ASTR + k0 + qd + 4]);
            #pragma unroll
            for (int nt = 0; nt < 8; ++nt) {
                uint32_t bb[2];
                bb[0] = __float_as_uint(Ks[(nt * 8 + grp) * ASTR + k0 + qd]);
                bb[1] = __float_as_uint(Ks[(nt * 8 + grp) * ASTR + k0 + qd + 4]);
                MMA_TF32(sacc[nt], a, bb);
            }
        }
        #pragma unroll
        for (int nt = 0; nt < 8; ++nt)
            #pragma unroll
            for (int r = 0; r < 4; ++r) sacc[nt][r] *= 0.125f;

        // ---- mask (slow path only when tile has zeros) ----
        if (flags[qt * 32 + st] == 0) {
            const int r0g = qbase + m0 + grp, r1g = r0g + 8;
            #pragma unroll
            for (int nt = 0; nt < 8; ++nt) {
                const int c0 = sbase + nt * 8 + 2 * qd;
                if (mask[(size_t)r0g * LL + c0    ] == 0) sacc[nt][0] = -INFINITY;
                if (mask[(size_t)r0g * LL + c0 + 1] == 0) sacc[nt][1] = -INFINITY;
                if (mask[(size_t)r1g * LL + c0    ] == 0) sacc[nt][2] = -INFINITY;
                if (mask[(size_t)r1g * LL + c0 + 1] == 0) sacc[nt][3] = -INFINITY;
            }
        }

        // ---- online softmax (rows grp, grp+8; reduce over quad lanes) ----
        float rm0 = -INFINITY, rm1 = -INFINITY;
        #pragma unroll
        for (int nt = 0; nt < 8; ++nt) {
            rm0 = fmaxf(rm0, fmaxf(sacc[nt][0], sacc[nt][1]));
            rm1 = fmaxf(rm1, fmaxf(sacc[nt][2], sacc[nt][3]));
        }
        rm0 = fmaxf(rm0, __shfl_xor_sync(0xffffffffu, rm0, 1));
        rm0 = fmaxf(rm0, __shfl_xor_sync(0xffffffffu, rm0, 2));
        rm1 = fmaxf(rm1, __shfl_xor_sync(0xffffffffu, rm1, 1));
        rm1 = fmaxf(rm1, __shfl_xor_sync(0xffffffffu, rm1, 2));
        const float mn0 = fmaxf(m_0, rm0), mn1 = fmaxf(m_1, rm1);
        const float al0 = __expf(m_0 - mn0), al1 = __expf(m_1 - mn1);
        m_0 = mn0; m_1 = mn1;

        float s0 = 0.f, s1 = 0.f;
        #pragma unroll
        for (int nt = 0; nt < 8; ++nt) {
            // round p to tf32 BEFORE summation so P (used in MMA) and l agree
            float p0 = __uint_as_float(f2tf32(__expf(sacc[nt][0] - mn0)));
            float p1 = __uint_as_float(f2tf32(__expf(sacc[nt][1] - mn0)));
            float p2 = __uint_as_float(f2tf32(__expf(sacc[nt][2] - mn1)));
            float p3 = __uint_as_float(f2tf32(__expf(sacc[nt][3] - mn1)));
            sacc[nt][0] = p0; sacc[nt][1] = p1; sacc[nt][2] = p2; sacc[nt][3] = p3;
            s0 += p0 + p1; s1 += p2 + p3;
        }
        s0 += __shfl_xor_sync(0xffffffffu, s0, 1);
        s0 += __shfl_xor_sync(0xffffffffu, s0, 2);
        s1 += __shfl_xor_sync(0xffffffffu, s1, 1);
        s1 += __shfl_xor_sync(0xffffffffu, s1, 2);
        l_0 = l_0 * al0 + s0;
        l_1 = l_1 * al1 + s1;
        #pragma unroll
        for (int nt = 0; nt < 8; ++nt) {
            o[nt][0] *= al0; o[nt][1] *= al0;
            o[nt][2] *= al1; o[nt][3] *= al1;
        }

        // ---- O += P @ V  (A-frag from S C-frag via intra-quad shfl) ----
        const int srl = (lane & ~3) | (qd >> 1);   // source lane for col qd
        #pragma unroll
        for (int ks = 0; ks < 8; ++ks) {
            uint32_t a[4];
            {
                float t0 = __shfl_sync(0xffffffffu, sacc[ks][0], srl);
                float t1 = __shfl_sync(0xffffffffu, sacc[ks][1], srl);
                float u0 = __shfl_sync(0xffffffffu, sacc[ks][0], srl + 2);
                float u1 = __shfl_sync(0xffffffffu, sacc[ks][1], srl + 2);
                a[0] = __float_as_uint((qd & 1) ? t1 : t0);
                a[2] = __float_as_uint((qd & 1) ? u1 : u0);
                t0 = __shfl_sync(0xffffffffu, sacc[ks][2], srl);
                t1 = __shfl_sync(0xffffffffu, sacc[ks][3], srl);
                u0 = __shfl_sync(0xffffffffu, sacc[ks][2], srl + 2);
                u1 = __shfl_sync(0xffffffffu, sacc[ks][3], srl + 2);
                a[1] = __float_as_uint((qd & 1) ? t1 : t0);
                a[3] = __float_as_uint((qd & 1) ? u1 : u0);
            }
            const int k0 = ks * 8;
            #pragma unroll
            for (int nt = 0; nt < 8; ++nt) {
                uint32_t bb[2];
                bb[0] = __float_as_uint(Vs[(k0 + qd    ) * VSTR + nt * 8 + grp]);
                bb[1] = __float_as_uint(Vs[(k0 + qd + 4) * VSTR + nt * 8 + grp]);
                MMA_TF32(o[nt], a, bb);
            }
        }
    }

    // ---- normalize + write (head-concat [B,L,D]) ----
    const float li0 = 1.f / l_0, li1 = 1.f / l_1;
    const int r0g = qbase + m0 + grp;
    #pragma unroll
    for (int nt = 0; nt < 8; ++nt) {
        const int col = head * HD + nt * 8 + 2 * qd;
        float2 w0 = make_float2(o[nt][0] * li0, o[nt][1] * li0);
        float2 w1 = make_float2(o[nt][2] * li1, o[nt][3] * li1);
        *(float2*)&vals[((size_t)(b * LL + r0g    )) * DD + col] = w0;
        *(float2*)&vals[((size_t)(b * LL + r0g + 8)) * DD + col] = w1;
    }
}

// ---------------------------------------------------------------------------
// Fused residual-add + LayerNorm (unchanged).
// ---------------------------------------------------------------------------
__global__ __launch_bounds__(128)
void add_ln(const float* __restrict__ a, const float* __restrict__ bres,
            const float* __restrict__ g, const float* __restrict__ beta,
            float* __restrict__ out)
{
    const int row = blockIdx.x;
    const int tid = threadIdx.x;

    float4 av = ((const float4*)(a    + (size_t)row * DD))[tid];
    float4 bv = ((const float4*)(bres + (size_t)row * DD))[tid];
    float4 x = make_float4(av.x+bv.x, av.y+bv.y, av.z+bv.z, av.w+bv.w);

    float s  = x.x + x.y + x.z + x.w;
    float ss = x.x*x.x + x.y*x.y + x.z*x.z + x.w*x.w;

    #pragma unroll
    for (int o = 16; o > 0; o >>= 1) {
        s  += __shfl_xor_sync(0xffffffffu, s,  o);
        ss += __shfl_xor_sync(0xffffffffu, ss, o);
    }
    __shared__ float red[2][4];
    const int w = tid >> 5, l = tid & 31;
    if (l == 0) { red[0][w] = s; red[1][w] = ss; }
    __syncthreads();
    s  = red[0][0] + red[0][1] + red[0][2] + red[0][3];
    ss = red[1][0] + red[1][1] + red[1][2] + red[1][3];

    const float mean = s * (1.f / DD);
    const float var  = ss * (1.f / DD) - mean * mean;
    const float rstd = rsqrtf(var + 1e-5f);

    float4 gv = ((const float4*)g)[tid];
    float4 ev = ((const float4*)beta)[tid];
    float4 o;
    o.x = (x.x - mean) * rstd * gv.x + ev.x;
    o.y = (x.y - mean) * rstd * gv.y + ev.y;
    o.z = (x.z - mean) * rstd * gv.z + ev.z;
    o.w = (x.w - mean) * rstd * gv.w + ev.w;
    ((float4*)(out + (size_t)row * DD))[tid] = o;
}

// ---------------------------------------------------------------------------
extern "C" void kernel_launch(void* const* d_in, const int* in_sizes, int n_in,
                              void* d_out, int out_size)
{
    const float* src    = (const float*)d_in[0];
    const int*   mask   = (const int*)  d_in[1];
    const float* qkv_w  = (const float*)d_in[2];
    const float* qkv_b  = (const float*)d_in[3];
    const float* out_w  = (const float*)d_in[4];
    const float* out_b  = (const float*)d_in[5];
    const float* w1     = (const float*)d_in[6];
    const float* b1     = (const float*)d_in[7];
    const float* w2     = (const float*)d_in[8];
    const float* b2     = (const float*)d_in[9];
    const float* g1     = (const float*)d_in[10];
    const float* beta1  = (const float*)d_in[11];
    const float* g2     = (const float*)d_in[12];
    const float* beta2  = (const float*)d_in[13];
    float* out = (float*)d_out;

    void* p;
    cudaGetSymbolAddress(&p, g_qkv);   float* qkv   = (float*)p;
    cudaGetSymbolAddress(&p, g_vals);  float* vals  = (float*)p;
    cudaGetSymbolAddress(&p, g_tmp);   float* tmp   = (float*)p;
    cudaGetSymbolAddress(&p, g_x1);    float* x1    = (float*)p;
    cudaGetSymbolAddress(&p, g_ff);    float* ff    = (float*)p;
    cudaGetSymbolAddress(&p, g_mflag); int*   mflag = (int*)p;

    cudaFuncSetAttribute(mma_gemm<0>, cudaFuncAttributeMaxDynamicSharedMemorySize, GEMM_SMEM);
    cudaFuncSetAttribute(mma_gemm<1>, cudaFuncAttributeMaxDynamicSharedMemorySize, GEMM_SMEM);
    cudaFuncSetAttribute(flash_attn_mma, cudaFuncAttributeMaxDynamicSharedMemorySize, ATT_SMEM);

    // 0) mask tile flags (independent of GEMM chain)
    mask_flags<<<512, 256>>>(mask, mflag);

    // 1) QKV projection: [8192,512] @ [1536,512]^T -> [8192,1536]
    mma_gemm<0><<<dim3((3*DD)/128, MR/128), 256, GEMM_SMEM>>>(src, qkv_w, qkv_b, qkv, MR, 3*DD, DD);

    // 2) flash attention (mma.sync) -> g_vals [8192,512]
    flash_attn_mma<<<dim3(LL/128, HH, BB), 256, ATT_SMEM>>>(qkv, mask, mflag, vals);

    // 3) output projection
    mma_gemm<0><<<dim3(DD/128, MR/128), 256, GEMM_SMEM>>>(vals, out_w, out_b, tmp, MR, DD, DD);

    // 4) x1 = LN(src + proj)
    add_ln<<<MR, 128>>>(src, tmp, g1, beta1, x1);

    // 5) FFN1 + ReLU: [8192,512] @ [2048,512]^T
    mma_gemm<1><<<dim3(DFF/128, MR/128), 256, GEMM_SMEM>>>(x1, w1, b1, ff, MR, DFF, DD);

    // 6) FFN2: [8192,2048] @ [512,2048]^T
    mma_gemm<0><<<dim3(DD/128, MR/128), 256, GEMM_SMEM>>>(ff, w2, b2, tmp, MR, DD, DFF);

    // 7) out = LN(x1 + ffn2)
    add_ln<<<MR, 128>>>(x1, tmp, g2, beta2, out);
}